// round 13
// baseline (speedup 1.0000x reference)
#include <cuda_runtime.h>
#include <cstdint>

#define T_DIM 512
#define B_DIM 512
#define I_DIM 100
#define H_DIM 96
#define G_DIM 288   // 3*H

// Scratch for input projections: [dir][t][b][3H]  (604 MB, static device alloc — allowed)
__device__ float g_xp[2][T_DIM][B_DIM][G_DIM];

// ---------------------------------------------------------------------------
// packed f32x2 ops (Blackwell)
// ---------------------------------------------------------------------------
__device__ __forceinline__ float2 ffma2(float2 a, float2 b, float2 c) {
    float2 d;
    asm("fma.rn.f32x2 %0, %1, %2, %3;"
        : "=l"(*reinterpret_cast<unsigned long long*>(&d))
        : "l"(*reinterpret_cast<unsigned long long*>(&a)),
          "l"(*reinterpret_cast<unsigned long long*>(&b)),
          "l"(*reinterpret_cast<unsigned long long*>(&c)));
    return d;
}
__device__ __forceinline__ float2 fadd2(float2 a, float2 b) {
    float2 d;
    asm("add.rn.f32x2 %0, %1, %2;"
        : "=l"(*reinterpret_cast<unsigned long long*>(&d))
        : "l"(*reinterpret_cast<unsigned long long*>(&a)),
          "l"(*reinterpret_cast<unsigned long long*>(&b)));
    return d;
}

__device__ __forceinline__ float sigmoidf_fast(float x) {
    return __fdividef(1.0f, 1.0f + __expf(-x));
}
__device__ __forceinline__ float tanhf_fast(float x) {
    return 2.0f * __fdividef(1.0f, 1.0f + __expf(-2.0f * x)) - 1.0f;
}

// ---------------------------------------------------------------------------
// Kernel 1: input projection, register-blocked 4 cols x 8 rows per thread
// (unchanged from rounds 10/11). grid (74, 2, 2), block 288, 2 CTAs/SM.
// ---------------------------------------------------------------------------
#define PROJ_TM 64
#define GH 144
#define WS2_STRIDE 145
#define XS_STRIDE 68

extern __shared__ float proj_sm[];

__global__ void __launch_bounds__(288, 2)
proj_kernel(const float* __restrict__ x,
            const float* __restrict__ w_f, const float* __restrict__ b_f,
            const float* __restrict__ w_b, const float* __restrict__ b_b)
{
    float* Ws = proj_sm;                        // [100][145]
    float* Xs = proj_sm + I_DIM * WS2_STRIDE;   // [100][68]

    const int dir   = blockIdx.y;
    const int ghalf = blockIdx.z;
    const float* __restrict__ W    = dir ? w_b : w_f;
    const float* __restrict__ bias = dir ? b_b : b_f;
    const int tid = threadIdx.x;
    const int gl  = tid % 36;         // local column base
    const int rh  = tid / 36;         // row octet (0..7)

    for (int idx = tid; idx < GH * I_DIM; idx += 288) {
        int gg = idx / I_DIM;
        int k  = idx - gg * I_DIM;
        Ws[k * WS2_STRIDE + gg] = W[(size_t)(ghalf * GH + gg) * I_DIM + k];
    }
    float bg[4];
    #pragma unroll
    for (int cc = 0; cc < 4; cc++) bg[cc] = bias[ghalf * GH + gl + 36 * cc];

    float* __restrict__ xp_base = &g_xp[dir][0][0][0];

    const int ntiles = (T_DIM * B_DIM) / PROJ_TM;   // 4096
    for (int tile = blockIdx.x; tile < ntiles; tile += gridDim.x) {
        const size_t row0 = (size_t)tile * PROJ_TM;

        __syncthreads();
        for (int idx = tid; idx < PROJ_TM * I_DIM; idx += 288) {
            int r = idx / I_DIM;
            int k = idx - r * I_DIM;
            Xs[k * XS_STRIDE + r] = x[(row0 + r) * I_DIM + k];
        }
        __syncthreads();

        float2 acc[4][4];
        #pragma unroll
        for (int cc = 0; cc < 4; cc++)
            #pragma unroll
            for (int p = 0; p < 4; p++) acc[cc][p] = make_float2(bg[cc], bg[cc]);

        #pragma unroll 4
        for (int k = 0; k < I_DIM; k++) {
            const float* xr = &Xs[k * XS_STRIDE + rh * 8];
            float4 xA = *reinterpret_cast<const float4*>(xr);
            float4 xB = *reinterpret_cast<const float4*>(xr + 4);
            float2 h01 = make_float2(xA.x, xA.y);
            float2 h23 = make_float2(xA.z, xA.w);
            float2 h45 = make_float2(xB.x, xB.y);
            float2 h67 = make_float2(xB.z, xB.w);
            #pragma unroll
            for (int cc = 0; cc < 4; cc++) {
                float w = Ws[k * WS2_STRIDE + gl + 36 * cc];
                float2 wp = make_float2(w, w);
                acc[cc][0] = ffma2(h01, wp, acc[cc][0]);
                acc[cc][1] = ffma2(h23, wp, acc[cc][1]);
                acc[cc][2] = ffma2(h45, wp, acc[cc][2]);
                acc[cc][3] = ffma2(h67, wp, acc[cc][3]);
            }
        }

        float* __restrict__ outp =
            xp_base + (row0 + rh * 8) * G_DIM + ghalf * GH + gl;
        #pragma unroll
        for (int cc = 0; cc < 4; cc++) {
            #pragma unroll
            for (int p = 0; p < 4; p++) {
                outp[(size_t)(2 * p)     * G_DIM + 36 * cc] = acc[cc][p].x;
                outp[(size_t)(2 * p + 1) * G_DIM + 36 * cc] = acc[cc][p].y;
            }
        }
    }
}

// ---------------------------------------------------------------------------
// Kernel 2: GRU scan with TWO independent 4-row groups per CTA.
// grid (64, 2), block 384 (12 warps, 1 CTA/SM — register-file bound).
// Thread = (j in [0,96), kq in [0,4)): gate triple {j,j+96,j+192} over
// k in {kq + 4i : i<24} (72 W regs). Accumulates 4 rows of group A and
// 4 rows of group B (12 f32x2) in one fused k-loop -> two fully independent
// dependency chains per phase (matvec, shfl-reduce, gates), giving the
// scheduler material to hide the 26-cyc SHFL / MUFU tail at 3 warps/SMSP.
// Value-splitting tree reduce per group: lane kq ends owning row kq.
// h double-buffered in smem -> ONE barrier per step.
// ---------------------------------------------------------------------------
#define KPT 24   // k-values per thread

__global__ void __launch_bounds__(384, 1)
scan_kernel(const float* __restrict__ whh_f, const float* __restrict__ bhh_f,
            const float* __restrict__ whh_b, const float* __restrict__ bhh_b,
            float* __restrict__ out)
{
    // [buf][group][k][r], r stride 4 (16B rows -> single LDS.128 per (k,group))
    __shared__ __align__(16) float h_s[2][2][H_DIM * 4];

    const int dir = blockIdx.y;
    const float* __restrict__ Whh = dir ? whh_b : whh_f;
    const float* __restrict__ bhh = dir ? bhh_b : bhh_f;
    const int tid = threadIdx.x;
    const int j   = tid >> 2;          // 0..95  (gate triple)
    const int kq  = tid & 3;           // 0..3   (k quarter; also owned row)
    const int b0  = blockIdx.x * 8;    // group A rows b0..b0+3, B rows b0+4..b0+7
    const bool hi_blk  = (kq & 2) != 0;
    const bool hi_pair = (kq & 1) != 0;

    // W_hh columns j / j+96 / j+192 at k = kq + 4i  -> 72 registers
    float wr[KPT], wz[KPT], wn[KPT];
    #pragma unroll
    for (int i = 0; i < KPT; i++) {
        int k = kq + 4 * i;
        wr[i] = Whh[(size_t)j * H_DIM + k];
        wz[i] = Whh[(size_t)(j + 96) * H_DIM + k];
        wn[i] = Whh[(size_t)(j + 192) * H_DIM + k];
    }
    const float br = (kq == 0) ? bhh[j]       : 0.0f;   // bias counted once per row-sum
    const float bz = (kq == 0) ? bhh[j + 96]  : 0.0f;
    const float bn = (kq == 0) ? bhh[j + 192] : 0.0f;

    // h0 = 0 (both buffers, both groups) + register-resident h_old per group
    for (int i = tid; i < 2 * 2 * H_DIM * 4; i += 384)
        (&h_s[0][0][0])[i] = 0.0f;
    float holdA = 0.0f, holdB = 0.0f;
    __syncthreads();

    const float* __restrict__ xp_dir = &g_xp[dir][0][0][0];

    for (int s = 0; s < T_DIM; s++) {
        const int t = dir ? (T_DIM - 1 - s) : s;

        // Prefetch x-projections: group A row b0+kq, group B row b0+4+kq
        const float* __restrict__ pA =
            xp_dir + ((size_t)t * B_DIM + b0 + kq) * G_DIM + j;
        const float* __restrict__ pB = pA + (size_t)4 * G_DIM;
        float xrA = pA[0], xzA = pA[96], xnA = pA[192];
        float xrB = pB[0], xzB = pB[96], xnB = pB[192];

        // Fused partial matvec for both groups (independent chains)
        const float* __restrict__ hbA = h_s[s & 1][0];
        const float* __restrict__ hbB = h_s[s & 1][1];
        float2 arA0 = make_float2(br, br), arA1 = arA0;
        float2 azA0 = make_float2(bz, bz), azA1 = azA0;
        float2 anA0 = make_float2(bn, bn), anA1 = anA0;
        float2 arB0 = arA0, arB1 = arA0;
        float2 azB0 = azA0, azB1 = azA0;
        float2 anB0 = anA0, anB1 = anA0;
        #pragma unroll
        for (int i = 0; i < KPT; i++) {
            int k = kq + 4 * i;
            float4 hA = *reinterpret_cast<const float4*>(&hbA[k * 4]);
            float4 hB = *reinterpret_cast<const float4*>(&hbB[k * 4]);
            float2 hA01 = make_float2(hA.x, hA.y);
            float2 hA23 = make_float2(hA.z, hA.w);
            float2 hB01 = make_float2(hB.x, hB.y);
            float2 hB23 = make_float2(hB.z, hB.w);
            float2 w2;
            w2 = make_float2(wr[i], wr[i]);
            arA0 = ffma2(hA01, w2, arA0); arA1 = ffma2(hA23, w2, arA1);
            arB0 = ffma2(hB01, w2, arB0); arB1 = ffma2(hB23, w2, arB1);
            w2 = make_float2(wz[i], wz[i]);
            azA0 = ffma2(hA01, w2, azA0); azA1 = ffma2(hA23, w2, azA1);
            azB0 = ffma2(hB01, w2, azB0); azB1 = ffma2(hB23, w2, azB1);
            w2 = make_float2(wn[i], wn[i]);
            anA0 = ffma2(hA01, w2, anA0); anA1 = ffma2(hA23, w2, anA1);
            anB0 = ffma2(hB01, w2, anB0); anB1 = ffma2(hB23, w2, anB1);
        }

        // Value-splitting tree reduce per group (warp-local over 4 kq lanes).
        // Round 1 (mask 2): keep own 2-row pair. Round 2 (mask 1): keep own row.
        // Lane kq ends with the full sum for row kq.
        #define XSWAP2(v, m, dst)                                       \
            { (dst).x = __shfl_xor_sync(0xFFFFFFFFu, (v).x, (m));       \
              (dst).y = __shfl_xor_sync(0xFFFFFFFFu, (v).y, (m)); }
        #define RED_GROUP(a0, a1, vout)                                 \
            {                                                           \
                float2 snd = hi_blk ? (a0) : (a1), rcv;                 \
                XSWAP2(snd, 2, rcv);                                    \
                float2 P = fadd2(hi_blk ? (a1) : (a0), rcv);            \
                float sS = hi_pair ? P.x : P.y;                         \
                float rS = __shfl_xor_sync(0xFFFFFFFFu, sS, 1);         \
                (vout) = (hi_pair ? P.y : P.x) + rS;                    \
            }
        float vrA, vzA, vnA, vrB, vzB, vnB;
        RED_GROUP(arA0, arA1, vrA)
        RED_GROUP(arB0, arB1, vrB)
        RED_GROUP(azA0, azA1, vzA)
        RED_GROUP(azB0, azB1, vzB)
        RED_GROUP(anA0, anA1, vnA)
        RED_GROUP(anB0, anB1, vnB)
        #undef RED_GROUP
        #undef XSWAP2

        // Gates (two independent rows, all in registers)
        float rgA = sigmoidf_fast(xrA + vrA);
        float rgB = sigmoidf_fast(xrB + vrB);
        float zgA = sigmoidf_fast(xzA + vzA);
        float zgB = sigmoidf_fast(xzB + vzB);
        float ngA = tanhf_fast(xnA + rgA * vnA);
        float ngB = tanhf_fast(xnB + rgB * vnB);
        float hnA = ngA + zgA * (holdA - ngA);
        float hnB = ngB + zgB * (holdB - ngB);
        holdA = hnA;
        holdB = hnB;

        // Write next-state buffers (parity s+1) + output
        h_s[(s + 1) & 1][0][j * 4 + kq] = hnA;   // index == tid: coalesced
        h_s[(s + 1) & 1][1][j * 4 + kq] = hnB;

        float* __restrict__ opA =
            out + ((size_t)t * B_DIM + b0 + kq) * (2 * H_DIM) + dir * H_DIM + j;
        opA[0]               = hnA;
        opA[4 * 2 * H_DIM]   = hnB;   // row b0+4+kq

        __syncthreads();   // buffers (s+1) complete; buffers s reads all done
    }
}

// ---------------------------------------------------------------------------
extern "C" void kernel_launch(void* const* d_in, const int* in_sizes, int n_in,
                              void* d_out, int out_size)
{
    const float* x      = (const float*)d_in[0];
    const float* w_ih_f = (const float*)d_in[1];
    const float* w_hh_f = (const float*)d_in[2];
    const float* b_ih_f = (const float*)d_in[3];
    const float* b_hh_f = (const float*)d_in[4];
    const float* w_ih_b = (const float*)d_in[5];
    const float* w_hh_b = (const float*)d_in[6];
    const float* b_ih_b = (const float*)d_in[7];
    const float* b_hh_b = (const float*)d_in[8];
    float* out = (float*)d_out;

    const int smem_proj = (I_DIM * WS2_STRIDE + I_DIM * XS_STRIDE) * sizeof(float); // 85.2 KB
    cudaFuncSetAttribute(proj_kernel, cudaFuncAttributeMaxDynamicSharedMemorySize, smem_proj);

    proj_kernel<<<dim3(74, 2, 2), 288, smem_proj>>>(x, w_ih_f, b_ih_f, w_ih_b, b_ih_b);
    scan_kernel<<<dim3(B_DIM / 8, 2), 384>>>(w_hh_f, b_hh_f, w_hh_b, b_hh_b, out);
}

// round 14
// speedup vs baseline: 1.1985x; 1.1985x over previous
#include <cuda_runtime.h>
#include <cstdint>

#define T_DIM 512
#define B_DIM 512
#define I_DIM 100
#define H_DIM 96
#define G_DIM 288   // 3*H

// Scratch for input projections: [dir][t][b][3H]  (604 MB, static device alloc — allowed)
__device__ float g_xp[2][T_DIM][B_DIM][G_DIM];

// ---------------------------------------------------------------------------
// packed f32x2 ops (Blackwell)
// ---------------------------------------------------------------------------
__device__ __forceinline__ float2 ffma2(float2 a, float2 b, float2 c) {
    float2 d;
    asm("fma.rn.f32x2 %0, %1, %2, %3;"
        : "=l"(*reinterpret_cast<unsigned long long*>(&d))
        : "l"(*reinterpret_cast<unsigned long long*>(&a)),
          "l"(*reinterpret_cast<unsigned long long*>(&b)),
          "l"(*reinterpret_cast<unsigned long long*>(&c)));
    return d;
}
__device__ __forceinline__ float2 fadd2(float2 a, float2 b) {
    float2 d;
    asm("add.rn.f32x2 %0, %1, %2;"
        : "=l"(*reinterpret_cast<unsigned long long*>(&d))
        : "l"(*reinterpret_cast<unsigned long long*>(&a)),
          "l"(*reinterpret_cast<unsigned long long*>(&b)));
    return d;
}

__device__ __forceinline__ float sigmoidf_fast(float x) {
    return __fdividef(1.0f, 1.0f + __expf(-x));
}
__device__ __forceinline__ float tanhf_fast(float x) {
    return 2.0f * __fdividef(1.0f, 1.0f + __expf(-2.0f * x)) - 1.0f;
}

// ---------------------------------------------------------------------------
// Kernel 1: input projection with DOUBLE-BUFFERED x tiles.
// grid (74, dir=2, ghalf=2) = 296 CTAs, block 288, 2 CTAs/SM.
// Thread = (gl in [0,36), rh in [0,8)): cols {4gl..4gl+3} (local), rows
// rh*8..+8 of a 64-row tile.
// Per k: 1 LDS.128 (W) + 2 LDS.128 (x, broadcast) feed 16 ffma2.
// Next tile's LDG+STS issue before this tile's compute -> fill hidden.
// Epilogue: 8 STG.128 (one float4 per row).
// Smem: Ws [100][148] (59.2KB) + Xs [2][100][68] (54.4KB) = 113.6KB/CTA.
// ---------------------------------------------------------------------------
#define PROJ_TM 64
#define GH 144
#define WS_STRIDE 148   // 592B rows: 16B-aligned for LDS.128
#define XS_STRIDE 68    // 272B rows: 16B-aligned

extern __shared__ float proj_sm[];

__global__ void __launch_bounds__(288, 2)
proj_kernel(const float* __restrict__ x,
            const float* __restrict__ w_f, const float* __restrict__ b_f,
            const float* __restrict__ w_b, const float* __restrict__ b_b)
{
    float* Ws  = proj_sm;                            // [100][148]
    float* Xs0 = proj_sm + I_DIM * WS_STRIDE;        // [100][68]
    float* Xs1 = Xs0 + I_DIM * XS_STRIDE;            // [100][68]

    const int dir   = blockIdx.y;
    const int ghalf = blockIdx.z;
    const float* __restrict__ W    = dir ? w_b : w_f;
    const float* __restrict__ bias = dir ? b_b : b_f;
    const int tid = threadIdx.x;
    const int gl  = tid % 36;         // local column quad: cols 4gl..4gl+3
    const int rh  = tid / 36;         // row octet (0..7)

    // Load this CTA's 144 W columns transposed: Ws[k][gg] = W[ghalf*144+gg][k]
    for (int idx = tid; idx < GH * I_DIM; idx += 288) {
        int gg = idx / I_DIM;
        int k  = idx - gg * I_DIM;
        Ws[k * WS_STRIDE + gg] = W[(size_t)(ghalf * GH + gg) * I_DIM + k];
    }
    float4 bg = *reinterpret_cast<const float4*>(bias + ghalf * GH + 4 * gl);

    float* __restrict__ xp_base = &g_xp[dir][0][0][0];

    const int ntiles = (T_DIM * B_DIM) / PROJ_TM;   // 4096
    const int stride = gridDim.x;                   // 74

    // Prologue: fill buffer 0 with the first tile
    {
        const size_t row0 = (size_t)blockIdx.x * PROJ_TM;
        for (int idx = tid; idx < PROJ_TM * I_DIM; idx += 288) {
            int r = idx / I_DIM;
            int k = idx - r * I_DIM;
            Xs0[k * XS_STRIDE + r] = x[(row0 + r) * I_DIM + k];
        }
    }
    __syncthreads();

    int buf = 0;
    for (int tile = blockIdx.x; tile < ntiles; tile += stride) {
        float* __restrict__ cur = buf ? Xs1 : Xs0;
        float* __restrict__ nxtb = buf ? Xs0 : Xs1;

        // Issue next tile's fill FIRST (LDG latency overlaps compute below)
        const int nxt = tile + stride;
        if (nxt < ntiles) {
            const size_t nrow0 = (size_t)nxt * PROJ_TM;
            for (int idx = tid; idx < PROJ_TM * I_DIM; idx += 288) {
                int r = idx / I_DIM;
                int k = idx - r * I_DIM;
                nxtb[k * XS_STRIDE + r] = x[(nrow0 + r) * I_DIM + k];
            }
        }

        // Compute current tile
        float2 acc[4][4];   // acc[cc][p]: col 4gl+cc, rows (2p, 2p+1)
        #pragma unroll
        for (int cc = 0; cc < 4; cc++)
            #pragma unroll
            for (int p = 0; p < 4; p++) {
                float b = (&bg.x)[cc];
                acc[cc][p] = make_float2(b, b);
            }

        #pragma unroll 4
        for (int k = 0; k < I_DIM; k++) {
            float4 wv = *reinterpret_cast<const float4*>(&Ws[k * WS_STRIDE + 4 * gl]);
            const float* xr = &cur[k * XS_STRIDE + rh * 8];
            float4 xA = *reinterpret_cast<const float4*>(xr);
            float4 xB = *reinterpret_cast<const float4*>(xr + 4);
            float2 h01 = make_float2(xA.x, xA.y);
            float2 h23 = make_float2(xA.z, xA.w);
            float2 h45 = make_float2(xB.x, xB.y);
            float2 h67 = make_float2(xB.z, xB.w);
            #pragma unroll
            for (int cc = 0; cc < 4; cc++) {
                float w = (&wv.x)[cc];
                float2 wp = make_float2(w, w);
                acc[cc][0] = ffma2(h01, wp, acc[cc][0]);
                acc[cc][1] = ffma2(h23, wp, acc[cc][1]);
                acc[cc][2] = ffma2(h45, wp, acc[cc][2]);
                acc[cc][3] = ffma2(h67, wp, acc[cc][3]);
            }
        }

        // Epilogue: one STG.128 per row (cols 4gl..4gl+3 contiguous)
        const size_t row0 = (size_t)tile * PROJ_TM;
        float* __restrict__ outp =
            xp_base + (row0 + rh * 8) * G_DIM + ghalf * GH + 4 * gl;
        #pragma unroll
        for (int p = 0; p < 4; p++) {
            float4 lo = make_float4(acc[0][p].x, acc[1][p].x, acc[2][p].x, acc[3][p].x);
            float4 hi = make_float4(acc[0][p].y, acc[1][p].y, acc[2][p].y, acc[3][p].y);
            *reinterpret_cast<float4*>(outp + (size_t)(2 * p)     * G_DIM) = lo;
            *reinterpret_cast<float4*>(outp + (size_t)(2 * p + 1) * G_DIM) = hi;
        }

        __syncthreads();   // next-buffer fill complete; current-buffer reads done
        buf ^= 1;
    }
}

// ---------------------------------------------------------------------------
// Kernel 2: single-phase GRU scan — EXACT round-9 version (measured 961us,
// the best of rounds 9/11/13). grid (64, 2), block 384 (12 warps).
// Thread = (j in [0,96), kq in [0,4)): gate triple {j,j+96,j+192} over
// k in {kq + 4i : i<24} (72 W regs), accumulates all 8 rows (12 f32x2).
// Butterfly all-reduce over 4 kq lanes; lane kq takes rows {2kq, 2kq+1}.
// h double-buffered in smem -> ONE barrier per step.
// ---------------------------------------------------------------------------
#define R_PER_CTA 8
#define KPT 24   // k-values per thread

__global__ void __launch_bounds__(384, 1)
scan_kernel(const float* __restrict__ whh_f, const float* __restrict__ bhh_f,
            const float* __restrict__ whh_b, const float* __restrict__ bhh_b,
            float* __restrict__ out)
{
    __shared__ __align__(16) float h_s[2][H_DIM * R_PER_CTA];   // double-buffered [k][r]

    const int dir = blockIdx.y;
    const float* __restrict__ Whh = dir ? whh_b : whh_f;
    const float* __restrict__ bhh = dir ? bhh_b : bhh_f;
    const int tid = threadIdx.x;
    const int j   = tid >> 2;          // 0..95  (gate triple)
    const int kq  = tid & 3;           // 0..3   (k quarter, warp-local lanes)
    const int b0  = blockIdx.x * R_PER_CTA;
    const int r0  = 2 * kq;            // rows owned in the gate phase

    // W_hh columns j / j+96 / j+192 at k = kq + 4i  -> 72 registers
    float wr[KPT], wz[KPT], wn[KPT];
    #pragma unroll
    for (int i = 0; i < KPT; i++) {
        int k = kq + 4 * i;
        wr[i] = Whh[(size_t)j * H_DIM + k];
        wz[i] = Whh[(size_t)(j + 96) * H_DIM + k];
        wn[i] = Whh[(size_t)(j + 192) * H_DIM + k];
    }
    const float br = (kq == 0) ? bhh[j]       : 0.0f;   // bias counted once
    const float bz = (kq == 0) ? bhh[j + 96]  : 0.0f;
    const float bn = (kq == 0) ? bhh[j + 192] : 0.0f;

    // h0 = 0 (both buffers) + register-resident h_old
    for (int i = tid; i < 2 * H_DIM * R_PER_CTA; i += 384)
        (&h_s[0][0])[i] = 0.0f;
    float hold0 = 0.0f, hold1 = 0.0f;
    __syncthreads();

    const float* __restrict__ xp_dir = &g_xp[dir][0][0][0];

    for (int s = 0; s < T_DIM; s++) {
        const int t = dir ? (T_DIM - 1 - s) : s;

        // Prefetch x-projections for this thread's 2 rows (consumed post-matvec)
        const float* __restrict__ p0 =
            xp_dir + ((size_t)t * B_DIM + b0 + r0) * G_DIM + j;
        const float* __restrict__ p1 = p0 + G_DIM;
        float xr0 = p0[0], xz0 = p0[96], xn0 = p0[192];
        float xr1 = p1[0], xz1 = p1[96], xn1 = p1[192];

        // Partial matvec over k = kq+4i for all 8 rows, 3 gate columns
        const float* __restrict__ hb = h_s[s & 1];
        float2 ar0 = make_float2(br, br), ar1 = ar0, ar2 = ar0, ar3 = ar0;
        float2 az0 = make_float2(bz, bz), az1 = az0, az2 = az0, az3 = az0;
        float2 an0 = make_float2(bn, bn), an1 = an0, an2 = an0, an3 = an0;
        #pragma unroll
        for (int i = 0; i < KPT; i++) {
            int k = kq + 4 * i;
            float4 hA = *reinterpret_cast<const float4*>(&hb[k * 8]);
            float4 hB = *reinterpret_cast<const float4*>(&hb[k * 8 + 4]);
            float2 h01 = make_float2(hA.x, hA.y);
            float2 h23 = make_float2(hA.z, hA.w);
            float2 h45 = make_float2(hB.x, hB.y);
            float2 h67 = make_float2(hB.z, hB.w);
            float2 w2;
            w2 = make_float2(wr[i], wr[i]);
            ar0 = ffma2(h01, w2, ar0); ar1 = ffma2(h23, w2, ar1);
            ar2 = ffma2(h45, w2, ar2); ar3 = ffma2(h67, w2, ar3);
            w2 = make_float2(wz[i], wz[i]);
            az0 = ffma2(h01, w2, az0); az1 = ffma2(h23, w2, az1);
            az2 = ffma2(h45, w2, az2); az3 = ffma2(h67, w2, az3);
            w2 = make_float2(wn[i], wn[i]);
            an0 = ffma2(h01, w2, an0); an1 = ffma2(h23, w2, an1);
            an2 = ffma2(h45, w2, an2); an3 = ffma2(h67, w2, an3);
        }

        // Butterfly all-reduce over the 4 kq lanes (warp-local)
        #define RED2(v, m)                                            \
            { float2 _o;                                              \
              _o.x = __shfl_xor_sync(0xFFFFFFFFu, (v).x, (m));        \
              _o.y = __shfl_xor_sync(0xFFFFFFFFu, (v).y, (m));        \
              (v) = fadd2((v), _o); }
        RED2(ar0, 1) RED2(ar1, 1) RED2(ar2, 1) RED2(ar3, 1)
        RED2(az0, 1) RED2(az1, 1) RED2(az2, 1) RED2(az3, 1)
        RED2(an0, 1) RED2(an1, 1) RED2(an2, 1) RED2(an3, 1)
        RED2(ar0, 2) RED2(ar1, 2) RED2(ar2, 2) RED2(ar3, 2)
        RED2(az0, 2) RED2(az1, 2) RED2(az2, 2) RED2(az3, 2)
        RED2(an0, 2) RED2(an1, 2) RED2(an2, 2) RED2(an3, 2)
        #undef RED2

        // Lane kq takes row-pair kq (uniform-per-thread select -> FSELs)
        float2 vr = (kq & 2) ? ((kq & 1) ? ar3 : ar2) : ((kq & 1) ? ar1 : ar0);
        float2 vz = (kq & 2) ? ((kq & 1) ? az3 : az2) : ((kq & 1) ? az1 : az0);
        float2 vn = (kq & 2) ? ((kq & 1) ? an3 : an2) : ((kq & 1) ? an1 : an0);

        // Gates for rows r0, r0+1 — entirely in registers
        float rg0 = sigmoidf_fast(xr0 + vr.x);
        float zg0 = sigmoidf_fast(xz0 + vz.x);
        float ng0 = tanhf_fast(xn0 + rg0 * vn.x);
        float hn0 = ng0 + zg0 * (hold0 - ng0);
        float rg1 = sigmoidf_fast(xr1 + vr.y);
        float zg1 = sigmoidf_fast(xz1 + vz.y);
        float ng1 = tanhf_fast(xn1 + rg1 * vn.y);
        float hn1 = ng1 + zg1 * (hold1 - ng1);
        hold0 = hn0;
        hold1 = hn1;

        // Write next-state buffer (parity s+1) + output
        float* __restrict__ hw = h_s[(s + 1) & 1];
        *reinterpret_cast<float2*>(&hw[j * 8 + r0]) = make_float2(hn0, hn1);

        float* __restrict__ op =
            out + ((size_t)t * B_DIM + b0 + r0) * (2 * H_DIM) + dir * H_DIM + j;
        op[0]         = hn0;
        op[2 * H_DIM] = hn1;

        __syncthreads();   // buffer (s+1) complete; buffer s reads all done
    }
}

// ---------------------------------------------------------------------------
extern "C" void kernel_launch(void* const* d_in, const int* in_sizes, int n_in,
                              void* d_out, int out_size)
{
    const float* x      = (const float*)d_in[0];
    const float* w_ih_f = (const float*)d_in[1];
    const float* w_hh_f = (const float*)d_in[2];
    const float* b_ih_f = (const float*)d_in[3];
    const float* b_hh_f = (const float*)d_in[4];
    const float* w_ih_b = (const float*)d_in[5];
    const float* w_hh_b = (const float*)d_in[6];
    const float* b_ih_b = (const float*)d_in[7];
    const float* b_hh_b = (const float*)d_in[8];
    float* out = (float*)d_out;

    const int smem_proj =
        (I_DIM * WS_STRIDE + 2 * I_DIM * XS_STRIDE) * sizeof(float);   // 113.6 KB
    cudaFuncSetAttribute(proj_kernel, cudaFuncAttributeMaxDynamicSharedMemorySize, smem_proj);

    proj_kernel<<<dim3(74, 2, 2), 288, smem_proj>>>(x, w_ih_f, b_ih_f, w_ih_b, b_ih_b);
    scan_kernel<<<dim3(B_DIM / R_PER_CTA, 2), 384>>>(w_hh_f, b_hh_f, w_hh_b, b_hh_b, out);
}